// round 9
// baseline (speedup 1.0000x reference)
#include <cuda_runtime.h>
#include <cuda_bf16.h>
#include <cstdint>

// ---------------- problem constants ----------------
constexpr int Mrows = 16384;          // B*C*T = 4*8*512
constexpr int K512  = 512;            // Gauss GEMM dims: M x 512 x 512

// GEMM tiling
constexpr int BM = 128, BN = 64, BK = 32;
constexpr int KSTEPS = K512 / BK;     // 16

// smem: rows padded to 40 bf16 = 80 B (conflict-free ldmatrix pattern, proven R8)
constexpr int ROWB = 80;
constexpr int A_TILE = BM * ROWB;             // 10240
constexpr int B_TILE = BN * ROWB;             // 5120
constexpr int ST_A = 0;                       // 6 A tiles: Xr hi/lo, Xi hi/lo, Xs hi/lo
constexpr int ST_B = 6 * A_TILE;              // 61440, 6 B tiles likewise
constexpr int STAGE = ST_B + 6 * B_TILE;      // 92160
constexpr int SMEM_BYTES = 2 * STAGE;         // 184320

constexpr size_t VS  = (size_t)Mrows * K512;  // X variant stride
constexpr size_t WVS = (size_t)K512 * K512;   // W variant stride

// ---------------- device scratch (allocation-free) ----------------
// variant order everywhere: 0=r_hi 1=r_lo 2=i_hi 3=i_lo 4=s_hi 5=s_lo  (s = r+i)
__device__ __nv_bfloat16 g_X[3][6][Mrows * K512];    // q,k,v input splits
__device__ __nv_bfloat16 g_A6[6][Mrows * K512];      // attention output splits (o input)
__device__ __nv_bfloat16 g_W6[4][6][K512 * K512];    // weight splits: q,k,v,o
__device__ float g_bR[4][K512];                      // br - bi
__device__ float g_bI[4][K512];                      // br + bi
__device__ float g_Qr[Mrows * K512];
__device__ float g_Qi[Mrows * K512];
__device__ float g_Kr[Mrows * K512];
__device__ float g_Ki[Mrows * K512];
__device__ float g_Vr[Mrows * K512];
__device__ float g_Vi[Mrows * K512];

// ---------------- PTX helpers (family-portable only) ----------------
#define CP_ASYNC16(dst, src) \
    asm volatile("cp.async.cg.shared.global [%0], [%1], 16;" :: "r"(dst), "l"(src))
#define CP_COMMIT() asm volatile("cp.async.commit_group;")
#define CP_WAIT(n)  asm volatile("cp.async.wait_group %0;" :: "n"(n))

#define LDSM_X4(r0, r1, r2, r3, addr) \
    asm volatile("ldmatrix.sync.aligned.m8n8.x4.shared.b16 {%0,%1,%2,%3}, [%4];" \
        : "=r"(r0), "=r"(r1), "=r"(r2), "=r"(r3) : "r"(addr))

__device__ __forceinline__ void mma_bf16(float* d, const uint32_t* a, uint32_t b0, uint32_t b1) {
    asm volatile(
        "mma.sync.aligned.m16n8k16.row.col.f32.bf16.bf16.f32 "
        "{%0,%1,%2,%3}, {%4,%5,%6,%7}, {%8,%9}, {%0,%1,%2,%3};"
        : "+f"(d[0]), "+f"(d[1]), "+f"(d[2]), "+f"(d[3])
        : "r"(a[0]), "r"(a[1]), "r"(a[2]), "r"(a[3]), "r"(b0), "r"(b1));
}

// ============================================================================
// pack weights: split Wr, Wi, Ws=Wr+Wi into bf16 hi/lo; biases br-bi, br+bi
// ============================================================================
__global__ void pack6(const float* __restrict__ Wr, const float* __restrict__ Wi,
                      const float* __restrict__ br, const float* __restrict__ bi,
                      __nv_bfloat16* __restrict__ W6, float* __restrict__ bR,
                      float* __restrict__ bI)
{
    int idx = blockIdx.x * 256 + threadIdx.x;     // over 262144
    float vr = Wr[idx], vi = Wi[idx], vs = vr + vi;
    float vals[3] = {vr, vi, vs};
#pragma unroll
    for (int p = 0; p < 3; p++) {
        __nv_bfloat16 h = __float2bfloat16(vals[p]);
        W6[(size_t)(2 * p) * WVS + idx] = h;
        W6[(size_t)(2 * p + 1) * WVS + idx] = __float2bfloat16(vals[p] - __bfloat162float(h));
    }
    if (idx < K512) {
        bR[idx] = br[idx] - bi[idx];
        bI[idx] = br[idx] + bi[idx];
    }
}

// ============================================================================
// split fp32 inputs into bf16 hi/lo for r, i, and s=r+i
// ============================================================================
struct alignas(8) BF4 { __nv_bfloat16 v[4]; };

__global__ void split3(const float* __restrict__ xr, const float* __restrict__ xi,
                       __nv_bfloat16* __restrict__ X)
{
    size_t i4 = (size_t)(blockIdx.x * 256 + threadIdx.x) * 4;   // over Mrows*K512
    float4 vr = *(const float4*)(xr + i4);
    float4 vi = *(const float4*)(xi + i4);
    float ar[4] = {vr.x, vr.y, vr.z, vr.w};
    float ai[4] = {vi.x, vi.y, vi.z, vi.w};
    BF4 out[6];
#pragma unroll
    for (int j = 0; j < 4; j++) {
        float vals[3] = {ar[j], ai[j], ar[j] + ai[j]};
#pragma unroll
        for (int p = 0; p < 3; p++) {
            __nv_bfloat16 h = __float2bfloat16(vals[p]);
            out[2 * p].v[j] = h;
            out[2 * p + 1].v[j] = __float2bfloat16(vals[p] - __bfloat162float(h));
        }
    }
#pragma unroll
    for (int v = 0; v < 6; v++)
        *(BF4*)(X + (size_t)v * VS + i4) = out[v];
}

// ============================================================================
// Gauss complex GEMM, bf16x3 on mma.sync:
//   P1 = Xr Wr^T, P2 = Xi Wi^T, P3 = Xs Ws^T   (each bf16x3: hh + hl + lh)
//   Yr = P1 - P2 + bR,  Yi = P3 - P1 - P2 + bI   (optional lrelu)
// BM=128 BN=64 BK=32, 512 threads (4x4 warps, tile 32x16), 3 accumulator sets.
// blockIdx.z selects layer (q,k,v merged in one launch).
// ============================================================================
struct GArg {
    const __nv_bfloat16* X;
    const __nv_bfloat16* W;
    const float* bR;
    const float* bI;
    float* oR;
    float* oI;
    int lrelu;
};
struct GArg3 { GArg a[3]; };

__global__ void __launch_bounds__(512, 1)
gemm_gauss(GArg3 all)
{
    const GArg g = all.a[blockIdx.z];
    extern __shared__ char smem[];
    const int tid = threadIdx.x;
    const int wid = tid >> 5, lane = tid & 31;
    const int wm = wid >> 2, wn = wid & 3;        // warp grid 4 x 4, tile 32 x 16
    const int r = lane >> 2, c = lane & 3;
    const int bm = blockIdx.x * BM, bn = blockIdx.y * BN;

    const uint32_t sb = (uint32_t)__cvta_generic_to_shared(smem);

    // ldmatrix per-lane offsets (proven R8 pattern)
    const int arow = (lane & 7) + ((lane >> 3) & 1) * 8;
    const int akof = ((lane >> 4) & 1) * 16;
    const uint32_t a_off = (uint32_t)((wm * 32 + arow) * ROWB + akof);
    const int brow = (lane & 7) + ((lane >> 4) & 1) * 8;
    const int bkof = ((lane >> 3) & 1) * 16;
    const uint32_t b_off = (uint32_t)((wn * 16 + brow) * ROWB + bkof);

    float acc[3][2][2][4];                        // [P][mi][n8][e]
#pragma unroll
    for (int p = 0; p < 3; p++)
#pragma unroll
        for (int mi = 0; mi < 2; mi++)
#pragma unroll
            for (int nj = 0; nj < 2; nj++)
#pragma unroll
                for (int e = 0; e < 4; e++) acc[p][mi][nj][e] = 0.f;

    // ---- async stage loader: 9x 16B per thread ----
    auto load_stage = [&](int s, int kt) {
        uint32_t base = sb + s * STAGE;
#pragma unroll
        for (int i = 0; i < 6; i++) {             // A: 6 variants x 128 rows x 4 chunks
            int cc = tid + i * 512;
            int v = cc >> 9, rc = cc & 511, row = rc >> 2, ch = rc & 3;
            const __nv_bfloat16* src = g.X + (size_t)v * VS + (size_t)(bm + row) * K512 + kt + ch * 8;
            CP_ASYNC16(base + ST_A + v * A_TILE + row * ROWB + ch * 16, src);
        }
#pragma unroll
        for (int i = 0; i < 3; i++) {             // B: 6 variants x 64 rows x 4 chunks
            int cc = tid + i * 512;
            int v = cc >> 8, rc = cc & 255, row = rc >> 2, ch = rc & 3;
            const __nv_bfloat16* src = g.W + (size_t)v * WVS + (size_t)(bn + row) * K512 + kt + ch * 8;
            CP_ASYNC16(base + ST_B + v * B_TILE + row * ROWB + ch * 16, src);
        }
        CP_COMMIT();
    };

    load_stage(0, 0);

    for (int s = 0; s < KSTEPS; s++) {
        if (s + 1 < KSTEPS) {
            load_stage((s + 1) & 1, (s + 1) * BK);
            CP_WAIT(1);
        } else {
            CP_WAIT(0);
        }
        __syncthreads();

        const uint32_t stb = sb + (s & 1) * STAGE;
#pragma unroll
        for (int kk = 0; kk < 2; kk++) {
            const uint32_t kb = stb + kk * 32;
#pragma unroll
            for (int p = 0; p < 3; p++) {
                uint32_t ah[2][4], al[2][4], bh[4], bl[4];
#pragma unroll
                for (int mi = 0; mi < 2; mi++) {
                    LDSM_X4(ah[mi][0], ah[mi][1], ah[mi][2], ah[mi][3],
                            kb + ST_A + (2 * p) * A_TILE + a_off + mi * (16 * ROWB));
                    LDSM_X4(al[mi][0], al[mi][1], al[mi][2], al[mi][3],
                            kb + ST_A + (2 * p + 1) * A_TILE + a_off + mi * (16 * ROWB));
                }
                LDSM_X4(bh[0], bh[1], bh[2], bh[3], kb + ST_B + (2 * p) * B_TILE + b_off);
                LDSM_X4(bl[0], bl[1], bl[2], bl[3], kb + ST_B + (2 * p + 1) * B_TILE + b_off);
#pragma unroll
                for (int mi = 0; mi < 2; mi++) {
                    mma_bf16(acc[p][mi][0], ah[mi], bh[0], bh[1]);
                    mma_bf16(acc[p][mi][0], ah[mi], bl[0], bl[1]);
                    mma_bf16(acc[p][mi][0], al[mi], bh[0], bh[1]);
                    mma_bf16(acc[p][mi][1], ah[mi], bh[2], bh[3]);
                    mma_bf16(acc[p][mi][1], ah[mi], bl[2], bl[3]);
                    mma_bf16(acc[p][mi][1], al[mi], bh[2], bh[3]);
                }
            }
        }
        __syncthreads();
    }

    // ---- epilogue: Gauss combine, bias, optional lrelu ----
#pragma unroll
    for (int mi = 0; mi < 2; mi++) {
#pragma unroll
        for (int nj = 0; nj < 2; nj++) {
            int ncol = bn + wn * 16 + nj * 8 + 2 * c;
            float br0 = g.bR[ncol], br1 = g.bR[ncol + 1];
            float bi0 = g.bI[ncol], bi1 = g.bI[ncol + 1];
            int row0 = bm + wm * 32 + mi * 16 + r;
#pragma unroll
            for (int hrow = 0; hrow < 2; hrow++) {
                float p1a = acc[0][mi][nj][2 * hrow + 0], p1b = acc[0][mi][nj][2 * hrow + 1];
                float p2a = acc[1][mi][nj][2 * hrow + 0], p2b = acc[1][mi][nj][2 * hrow + 1];
                float p3a = acc[2][mi][nj][2 * hrow + 0], p3b = acc[2][mi][nj][2 * hrow + 1];
                float yr0 = p1a - p2a + br0, yr1 = p1b - p2b + br1;
                float yi0 = p3a - p1a - p2a + bi0, yi1 = p3b - p1b - p2b + bi1;
                if (g.lrelu) {
                    yr0 = yr0 >= 0.f ? yr0 : 0.01f * yr0;
                    yr1 = yr1 >= 0.f ? yr1 : 0.01f * yr1;
                    yi0 = yi0 >= 0.f ? yi0 : 0.01f * yi0;
                    yi1 = yi1 >= 0.f ? yi1 : 0.01f * yi1;
                }
                size_t o = (size_t)(row0 + 8 * hrow) * K512 + ncol;
                *(float2*)&g.oR[o] = make_float2(yr0, yr1);
                *(float2*)&g.oI[o] = make_float2(yi0, yi1);
            }
        }
    }
}

// ============================================================================
// channel attention: per (b,h,t) 8x8 complex scores (no softmax), S@V, lrelu,
// write merged-head output splits (r,i,s hi/lo) directly for the o-GEMM
// ============================================================================
__global__ void attn_kernel()
{
    __shared__ float sm[6][8][68];
    __shared__ float ssr[8][9], ssi[8][9];

    const int t = blockIdx.x, h = blockIdx.y, b = blockIdx.z;
    const int tid = threadIdx.x;

    {
        int c = tid >> 4, d4 = (tid & 15) << 2;
        size_t base = (((size_t)(b * 8 + c) * 512 + t) * 512) + h * 64 + d4;
        *(float4*)&sm[0][c][d4] = *(const float4*)&g_Qr[base];
        *(float4*)&sm[1][c][d4] = *(const float4*)&g_Qi[base];
        *(float4*)&sm[2][c][d4] = *(const float4*)&g_Kr[base];
        *(float4*)&sm[3][c][d4] = *(const float4*)&g_Ki[base];
        *(float4*)&sm[4][c][d4] = *(const float4*)&g_Vr[base];
        *(float4*)&sm[5][c][d4] = *(const float4*)&g_Vi[base];
    }
    __syncthreads();

    if (tid < 64) {
        int cc = tid >> 3, e = tid & 7;
        float ar = 0.f, ai = 0.f;
#pragma unroll 8
        for (int d = 0; d < 64; d++) {
            float qr = sm[0][cc][d], qi = sm[1][cc][d];
            float kr = sm[2][e][d],  ki = sm[3][e][d];
            ar = fmaf(qr, kr, fmaf(qi, ki, ar));
            ai = fmaf(qr, ki, fmaf(-qi, kr, ai));
        }
        ssr[cc][e] = ar * 0.125f;
        ssi[cc][e] = ai * 0.125f;
    }
    __syncthreads();

#pragma unroll
    for (int i = 0; i < 4; i++) {
        int idx = tid + i * 128;
        int cc = idx >> 6, d = idx & 63;
        float xr = 0.f, xi = 0.f;
#pragma unroll
        for (int e = 0; e < 8; e++) {
            float sr_ = ssr[cc][e], si_ = ssi[cc][e];
            float vr = sm[4][e][d], vi = sm[5][e][d];
            xr = fmaf(sr_, vr, fmaf(-si_, vi, xr));
            xi = fmaf(si_, vr, fmaf(sr_, vi, xi));
        }
        xr = xr >= 0.f ? xr : 0.01f * xr;
        xi = xi >= 0.f ? xi : 0.01f * xi;
        float xs = xr + xi;
        size_t mrow = (size_t)(b * 8 + cc) * 512 + t;
        size_t o = mrow * K512 + h * 64 + d;       // merged-head col within 512
        float vals[3] = {xr, xi, xs};
#pragma unroll
        for (int p = 0; p < 3; p++) {
            __nv_bfloat16 hh = __float2bfloat16(vals[p]);
            g_A6[2 * p][o] = hh;
            g_A6[2 * p + 1][o] = __float2bfloat16(vals[p] - __bfloat162float(hh));
        }
    }
}

// ============================================================================
// host side: pack x4, split x3, gemm(q|k|v merged), attn, gemm(o)
// ============================================================================
extern "C" void kernel_launch(void* const* d_in, const int* in_sizes, int n_in,
                              void* d_out, int out_size)
{
    const float* in[22];
    for (int i = 0; i < 22; i++) in[i] = (const float*)d_in[i];

    void *X_, *A6_, *W6_, *bR_, *bI_, *Qr_, *Qi_, *Kr_, *Ki_, *Vr_, *Vi_;
    cudaGetSymbolAddress(&X_, g_X);
    cudaGetSymbolAddress(&A6_, g_A6);
    cudaGetSymbolAddress(&W6_, g_W6);
    cudaGetSymbolAddress(&bR_, g_bR);
    cudaGetSymbolAddress(&bI_, g_bI);
    cudaGetSymbolAddress(&Qr_, g_Qr);
    cudaGetSymbolAddress(&Qi_, g_Qi);
    cudaGetSymbolAddress(&Kr_, g_Kr);
    cudaGetSymbolAddress(&Ki_, g_Ki);
    cudaGetSymbolAddress(&Vr_, g_Vr);
    cudaGetSymbolAddress(&Vi_, g_Vi);

    __nv_bfloat16* X = (__nv_bfloat16*)X_;
    __nv_bfloat16* W6 = (__nv_bfloat16*)W6_;
    float* bR = (float*)bR_;
    float* bI = (float*)bI_;

    cudaFuncSetAttribute(gemm_gauss, cudaFuncAttributeMaxDynamicSharedMemorySize, SMEM_BYTES);

    // weights: 6=Wq_r 7=bq_r 8=Wq_i 9=bq_i | 10..13 k | 14..17 v | 18..21 o
    pack6<<<1024, 256>>>(in[6],  in[8],  in[7],  in[9],  W6 + 0 * 6 * WVS, bR + 0 * K512, bI + 0 * K512);
    pack6<<<1024, 256>>>(in[10], in[12], in[11], in[13], W6 + 1 * 6 * WVS, bR + 1 * K512, bI + 1 * K512);
    pack6<<<1024, 256>>>(in[14], in[16], in[15], in[17], W6 + 2 * 6 * WVS, bR + 2 * K512, bI + 2 * K512);
    pack6<<<1024, 256>>>(in[18], in[20], in[19], in[21], W6 + 3 * 6 * WVS, bR + 3 * K512, bI + 3 * K512);

    // input splits (q, k, v): Mrows*K512/4/256 = 8192 blocks
    split3<<<8192, 256>>>(in[0], in[1], X + 0 * 6 * VS);
    split3<<<8192, 256>>>(in[2], in[3], X + 1 * 6 * VS);
    split3<<<8192, 256>>>(in[4], in[5], X + 2 * 6 * VS);

    // q,k,v GEMMs merged into one launch (grid.z = 3)
    GArg3 qkv;
    float* outsR[3] = {(float*)Qr_, (float*)Kr_, (float*)Vr_};
    float* outsI[3] = {(float*)Qi_, (float*)Ki_, (float*)Vi_};
    for (int z = 0; z < 3; z++) {
        qkv.a[z].X = X + (size_t)z * 6 * VS;
        qkv.a[z].W = W6 + (size_t)z * 6 * WVS;
        qkv.a[z].bR = bR + z * K512;
        qkv.a[z].bI = bI + z * K512;
        qkv.a[z].oR = outsR[z];
        qkv.a[z].oI = outsI[z];
        qkv.a[z].lrelu = (z == 2) ? 1 : 0;
    }
    gemm_gauss<<<dim3(Mrows / BM, K512 / BN, 3), 512, SMEM_BYTES>>>(qkv);

    attn_kernel<<<dim3(512, 8, 4), 128>>>();

    GArg3 og;
    og.a[0].X = (__nv_bfloat16*)A6_;
    og.a[0].W = W6 + (size_t)3 * 6 * WVS;
    og.a[0].bR = bR + 3 * K512;
    og.a[0].bI = bI + 3 * K512;
    og.a[0].oR = (float*)d_out;
    og.a[0].oI = (float*)d_out + (size_t)Mrows * K512;
    og.a[0].lrelu = 0;
    og.a[1] = og.a[0];
    og.a[2] = og.a[0];
    gemm_gauss<<<dim3(Mrows / BM, K512 / BN, 1), 512, SMEM_BYTES>>>(og);
}

// round 10
// speedup vs baseline: 1.8459x; 1.8459x over previous
#include <cuda_runtime.h>
#include <cuda_bf16.h>
#include <cstdint>

// ---------------- problem constants ----------------
constexpr int Mrows = 16384;          // B*C*T = 4*8*512
constexpr int K512  = 512;            // Gauss P-GEMM: M x 512 x 512

// GEMM tiling (exact R8 geometry)
constexpr int BM = 128, BN = 256, BK = 32;
constexpr int KSTEPS = K512 / BK;     // 16

// smem stage layout (bytes). Rows padded to 40 bf16 = 80 B (20 words) —
// ldmatrix 8-row phases hit disjoint bank quads (proven R8).
constexpr int ROWB = 80;
constexpr int ST_AHI = 0;
constexpr int ST_ALO = ST_AHI + BM * ROWB;      // 10240
constexpr int ST_BHI = ST_ALO + BM * ROWB;      // 20480
constexpr int ST_BLO = ST_BHI + BN * ROWB;      // 40960
constexpr int STAGE  = ST_BLO + BN * ROWB;      // 61440
constexpr int SMEM_BYTES = 2 * STAGE;           // 122880

constexpr size_t VS  = (size_t)Mrows * K512;    // X variant stride
constexpr size_t WVS = (size_t)K512 * K512;     // W variant stride
constexpr size_t PS  = (size_t)Mrows * K512;    // P buffer stride

// ---------------- device scratch (allocation-free) ----------------
// variant order: 0=r_hi 1=r_lo 2=i_hi 3=i_lo 4=s_hi 5=s_lo   (s = r+i)
__device__ __nv_bfloat16 g_X[3][6][Mrows * K512];    // q,k,v input splits
__device__ __nv_bfloat16 g_A6[6][Mrows * K512];      // attention output splits (o input)
__device__ __nv_bfloat16 g_W6[4][6][K512 * K512];    // weight splits: q,k,v,o
__device__ float g_bR[4][K512];                      // br - bi
__device__ float g_bI[4][K512];                      // br + bi
__device__ float g_P[9][Mrows * K512];               // QKV products: layer*3 + p
__device__ float g_Po[3][Mrows * K512];              // o-layer products

// ---------------- PTX helpers (family-portable only) ----------------
#define CP_ASYNC16(dst, src) \
    asm volatile("cp.async.cg.shared.global [%0], [%1], 16;" :: "r"(dst), "l"(src))
#define CP_COMMIT() asm volatile("cp.async.commit_group;")
#define CP_WAIT(n)  asm volatile("cp.async.wait_group %0;" :: "n"(n))

#define LDSM_X4(r0, r1, r2, r3, addr) \
    asm volatile("ldmatrix.sync.aligned.m8n8.x4.shared.b16 {%0,%1,%2,%3}, [%4];" \
        : "=r"(r0), "=r"(r1), "=r"(r2), "=r"(r3) : "r"(addr))

__device__ __forceinline__ void mma_bf16(float* d, const uint32_t* a, uint32_t b0, uint32_t b1) {
    asm volatile(
        "mma.sync.aligned.m16n8k16.row.col.f32.bf16.bf16.f32 "
        "{%0,%1,%2,%3}, {%4,%5,%6,%7}, {%8,%9}, {%0,%1,%2,%3};"
        : "+f"(d[0]), "+f"(d[1]), "+f"(d[2]), "+f"(d[3])
        : "r"(a[0]), "r"(a[1]), "r"(a[2]), "r"(a[3]), "r"(b0), "r"(b1));
}

// ============================================================================
// pack weights: split Wr, Wi, Ws=Wr+Wi into bf16 hi/lo; biases br-bi, br+bi
// ============================================================================
__global__ void pack6(const float* __restrict__ Wr, const float* __restrict__ Wi,
                      const float* __restrict__ br, const float* __restrict__ bi,
                      __nv_bfloat16* __restrict__ W6, float* __restrict__ bR,
                      float* __restrict__ bI)
{
    int idx = blockIdx.x * 256 + threadIdx.x;     // over 262144
    float vr = Wr[idx], vi = Wi[idx], vs = vr + vi;
    float vals[3] = {vr, vi, vs};
#pragma unroll
    for (int p = 0; p < 3; p++) {
        __nv_bfloat16 h = __float2bfloat16(vals[p]);
        W6[(size_t)(2 * p) * WVS + idx] = h;
        W6[(size_t)(2 * p + 1) * WVS + idx] = __float2bfloat16(vals[p] - __bfloat162float(h));
    }
    if (idx < K512) {
        bR[idx] = br[idx] - bi[idx];
        bI[idx] = br[idx] + bi[idx];
    }
}

// ============================================================================
// split fp32 inputs into bf16 hi/lo for r, i, and s=r+i
// ============================================================================
struct alignas(8) BF4 { __nv_bfloat16 v[4]; };

__global__ void split3(const float* __restrict__ xr, const float* __restrict__ xi,
                       __nv_bfloat16* __restrict__ X)
{
    size_t i4 = (size_t)(blockIdx.x * 256 + threadIdx.x) * 4;   // over Mrows*K512
    float4 vr = *(const float4*)(xr + i4);
    float4 vi = *(const float4*)(xi + i4);
    float ar[4] = {vr.x, vr.y, vr.z, vr.w};
    float ai[4] = {vi.x, vi.y, vi.z, vi.w};
    BF4 out[6];
#pragma unroll
    for (int j = 0; j < 4; j++) {
        float vals[3] = {ar[j], ai[j], ar[j] + ai[j]};
#pragma unroll
        for (int p = 0; p < 3; p++) {
            __nv_bfloat16 h = __float2bfloat16(vals[p]);
            out[2 * p].v[j] = h;
            out[2 * p + 1].v[j] = __float2bfloat16(vals[p] - __bfloat162float(h));
        }
    }
#pragma unroll
    for (int v = 0; v < 6; v++)
        *(BF4*)(X + (size_t)v * VS + i4) = out[v];
}

// ============================================================================
// P-GEMM (R8 geometry, K=512): P = X_v @ W_v^T with bf16x3 (hh + hl + lh)
// mode 0: QKV (z = layer*3 + p), mode 1: O (z = p)
// BM=128 BN=256 BK=32, 512 threads (4x4 warps, warp tile 32x64).
// ============================================================================
__global__ void __launch_bounds__(512, 1)
gemm_p(int mode)
{
    const int z = blockIdx.z;
    const __nv_bfloat16 *Ahi_g, *Alo_g, *Bhi_g, *Blo_g;
    float* Pout;
    if (mode == 0) {
        int layer = z / 3, p = z - 3 * layer;
        Ahi_g = g_X[layer][2 * p];
        Alo_g = g_X[layer][2 * p + 1];
        Bhi_g = g_W6[layer][2 * p];
        Blo_g = g_W6[layer][2 * p + 1];
        Pout  = g_P[z];
    } else {
        Ahi_g = g_A6[2 * z];
        Alo_g = g_A6[2 * z + 1];
        Bhi_g = g_W6[3][2 * z];
        Blo_g = g_W6[3][2 * z + 1];
        Pout  = g_Po[z];
    }

    extern __shared__ char smem[];
    const int tid = threadIdx.x;
    const int wid = tid >> 5, lane = tid & 31;
    const int wm = wid >> 2, wn = wid & 3;        // warp grid 4 x 4, tile 32 x 64
    const int r = lane >> 2, c = lane & 3;
    const int bm = blockIdx.x * BM, bn = blockIdx.y * BN;

    const uint32_t sb = (uint32_t)__cvta_generic_to_shared(smem);

    const int arow = (lane & 7) + ((lane >> 3) & 1) * 8;
    const int akof = ((lane >> 4) & 1) * 16;
    const uint32_t a_off = (uint32_t)((wm * 32 + arow) * ROWB + akof);
    const int brow = (lane & 7) + ((lane >> 4) & 1) * 8;
    const int bkof = ((lane >> 3) & 1) * 16;
    const uint32_t b_off = (uint32_t)((wn * 64 + brow) * ROWB + bkof);

    float acc[2][8][4];
#pragma unroll
    for (int mi = 0; mi < 2; mi++)
#pragma unroll
        for (int nj = 0; nj < 8; nj++)
#pragma unroll
            for (int e = 0; e < 4; e++) acc[mi][nj][e] = 0.f;

    auto load_stage = [&](int s, int kt) {
        uint32_t base = sb + s * STAGE;
        {
            int row = tid >> 2, ch = tid & 3;
            size_t go = (size_t)(bm + row) * K512 + kt + ch * 8;
            CP_ASYNC16(base + ST_AHI + row * ROWB + ch * 16, Ahi_g + go);
            CP_ASYNC16(base + ST_ALO + row * ROWB + ch * 16, Alo_g + go);
        }
#pragma unroll
        for (int i = 0; i < 2; i++) {
            int j = tid + i * 512;
            int row = j >> 2, ch = j & 3;
            size_t go = (size_t)(bn + row) * K512 + kt + ch * 8;
            CP_ASYNC16(base + ST_BHI + row * ROWB + ch * 16, Bhi_g + go);
            CP_ASYNC16(base + ST_BLO + row * ROWB + ch * 16, Blo_g + go);
        }
        CP_COMMIT();
    };

    load_stage(0, 0);

    for (int s = 0; s < KSTEPS; s++) {
        if (s + 1 < KSTEPS) {
            load_stage((s + 1) & 1, (s + 1) * BK);
            CP_WAIT(1);
        } else {
            CP_WAIT(0);
        }
        __syncthreads();

        const uint32_t stb = sb + (s & 1) * STAGE;
#pragma unroll
        for (int kk = 0; kk < 2; kk++) {
            const uint32_t kb = stb + kk * 32;
            uint32_t ah[2][4], al[2][4];
#pragma unroll
            for (int mi = 0; mi < 2; mi++) {
                LDSM_X4(ah[mi][0], ah[mi][1], ah[mi][2], ah[mi][3],
                        kb + ST_AHI + a_off + mi * (16 * ROWB));
                LDSM_X4(al[mi][0], al[mi][1], al[mi][2], al[mi][3],
                        kb + ST_ALO + a_off + mi * (16 * ROWB));
            }
#pragma unroll
            for (int g = 0; g < 4; g++) {
                uint32_t bh[4], bl[4];
                LDSM_X4(bh[0], bh[1], bh[2], bh[3], kb + ST_BHI + b_off + g * (16 * ROWB));
                LDSM_X4(bl[0], bl[1], bl[2], bl[3], kb + ST_BLO + b_off + g * (16 * ROWB));
#pragma unroll
                for (int mi = 0; mi < 2; mi++) {
                    mma_bf16(acc[mi][2 * g + 0], ah[mi], bh[0], bh[1]);
                    mma_bf16(acc[mi][2 * g + 0], ah[mi], bl[0], bl[1]);
                    mma_bf16(acc[mi][2 * g + 0], al[mi], bh[0], bh[1]);
                    mma_bf16(acc[mi][2 * g + 1], ah[mi], bh[2], bh[3]);
                    mma_bf16(acc[mi][2 * g + 1], ah[mi], bl[2], bl[3]);
                    mma_bf16(acc[mi][2 * g + 1], al[mi], bh[2], bh[3]);
                }
            }
        }
        __syncthreads();
    }

    // ---- epilogue: raw fp32 P (no bias, no lrelu) ----
#pragma unroll
    for (int mi = 0; mi < 2; mi++) {
#pragma unroll
        for (int nj = 0; nj < 8; nj++) {
            int ncol = bn + wn * 64 + nj * 8 + 2 * c;
            int row0 = bm + wm * 32 + mi * 16 + r;
#pragma unroll
            for (int hrow = 0; hrow < 2; hrow++) {
                float2 o = make_float2(acc[mi][nj][2 * hrow + 0], acc[mi][nj][2 * hrow + 1]);
                *(float2*)&Pout[(size_t)(row0 + 8 * hrow) * K512 + ncol] = o;
            }
        }
    }
}

// ============================================================================
// channel attention with fused Gauss combine of Q/K/V:
//   qr = P1-P2+bR, qi = P3-P1-P2+bI (same for k, v; lrelu on v)
// then 8x8 complex scores (no softmax), S@V, lrelu, write o-GEMM input splits.
// ============================================================================
__global__ void attn_kernel()
{
    __shared__ float sm[6][8][68];
    __shared__ float ssr[8][9], ssi[8][9];

    const int t = blockIdx.x, h = blockIdx.y, b = blockIdx.z;
    const int tid = threadIdx.x;

    {
        int cch = tid >> 4, d4 = (tid & 15) << 2;
        size_t m = ((size_t)(b * 8 + cch) * 512 + t);
        size_t off = m * K512 + h * 64 + d4;
        int col = h * 64 + d4;

#pragma unroll
        for (int layer = 0; layer < 3; layer++) {
            float4 p1 = *(const float4*)&g_P[layer * 3 + 0][off];
            float4 p2 = *(const float4*)&g_P[layer * 3 + 1][off];
            float4 p3 = *(const float4*)&g_P[layer * 3 + 2][off];
            float4 br = *(const float4*)&g_bR[layer][col];
            float4 bi = *(const float4*)&g_bI[layer][col];
            float4 yr, yi;
            yr.x = p1.x - p2.x + br.x;  yi.x = p3.x - p1.x - p2.x + bi.x;
            yr.y = p1.y - p2.y + br.y;  yi.y = p3.y - p1.y - p2.y + bi.y;
            yr.z = p1.z - p2.z + br.z;  yi.z = p3.z - p1.z - p2.z + bi.z;
            yr.w = p1.w - p2.w + br.w;  yi.w = p3.w - p1.w - p2.w + bi.w;
            if (layer == 2) {   // lrelu on V
                yr.x = yr.x >= 0.f ? yr.x : 0.01f * yr.x;
                yr.y = yr.y >= 0.f ? yr.y : 0.01f * yr.y;
                yr.z = yr.z >= 0.f ? yr.z : 0.01f * yr.z;
                yr.w = yr.w >= 0.f ? yr.w : 0.01f * yr.w;
                yi.x = yi.x >= 0.f ? yi.x : 0.01f * yi.x;
                yi.y = yi.y >= 0.f ? yi.y : 0.01f * yi.y;
                yi.z = yi.z >= 0.f ? yi.z : 0.01f * yi.z;
                yi.w = yi.w >= 0.f ? yi.w : 0.01f * yi.w;
            }
            *(float4*)&sm[2 * layer + 0][cch][d4] = yr;
            *(float4*)&sm[2 * layer + 1][cch][d4] = yi;
        }
    }
    __syncthreads();

    if (tid < 64) {
        int cc = tid >> 3, e = tid & 7;
        float ar = 0.f, ai = 0.f;
#pragma unroll 8
        for (int d = 0; d < 64; d++) {
            float qr = sm[0][cc][d], qi = sm[1][cc][d];
            float kr = sm[2][e][d],  ki = sm[3][e][d];
            ar = fmaf(qr, kr, fmaf(qi, ki, ar));
            ai = fmaf(qr, ki, fmaf(-qi, kr, ai));
        }
        ssr[cc][e] = ar * 0.125f;
        ssi[cc][e] = ai * 0.125f;
    }
    __syncthreads();

#pragma unroll
    for (int i = 0; i < 4; i++) {
        int idx = tid + i * 128;
        int cc = idx >> 6, d = idx & 63;
        float xr = 0.f, xi = 0.f;
#pragma unroll
        for (int e = 0; e < 8; e++) {
            float sr_ = ssr[cc][e], si_ = ssi[cc][e];
            float vr = sm[4][e][d], vi = sm[5][e][d];
            xr = fmaf(sr_, vr, fmaf(-si_, vi, xr));
            xi = fmaf(si_, vr, fmaf(sr_, vi, xi));
        }
        xr = xr >= 0.f ? xr : 0.01f * xr;
        xi = xi >= 0.f ? xi : 0.01f * xi;
        float xs = xr + xi;
        size_t mrow = (size_t)(b * 8 + cc) * 512 + t;
        size_t o = mrow * K512 + h * 64 + d;
        float vals[3] = {xr, xi, xs};
#pragma unroll
        for (int p = 0; p < 3; p++) {
            __nv_bfloat16 hh = __float2bfloat16(vals[p]);
            g_A6[2 * p][o] = hh;
            g_A6[2 * p + 1][o] = __float2bfloat16(vals[p] - __bfloat162float(hh));
        }
    }
}

// ============================================================================
// o-layer Gauss combine: d_out = [Yr | Yi] from g_Po + biases
// ============================================================================
__global__ void combine_out(float* __restrict__ out)
{
    size_t i4 = (size_t)(blockIdx.x * 256 + threadIdx.x) * 4;   // over Mrows*K512
    int col = (int)(i4 & 511);
    float4 p1 = *(const float4*)&g_Po[0][i4];
    float4 p2 = *(const float4*)&g_Po[1][i4];
    float4 p3 = *(const float4*)&g_Po[2][i4];
    float4 br = *(const float4*)&g_bR[3][col];
    float4 bi = *(const float4*)&g_bI[3][col];
    float4 yr, yi;
    yr.x = p1.x - p2.x + br.x;  yi.x = p3.x - p1.x - p2.x + bi.x;
    yr.y = p1.y - p2.y + br.y;  yi.y = p3.y - p1.y - p2.y + bi.y;
    yr.z = p1.z - p2.z + br.z;  yi.z = p3.z - p1.z - p2.z + bi.z;
    yr.w = p1.w - p2.w + br.w;  yi.w = p3.w - p1.w - p2.w + bi.w;
    *(float4*)&out[i4] = yr;
    *(float4*)&out[(size_t)Mrows * K512 + i4] = yi;
}

// ============================================================================
// host side
// ============================================================================
extern "C" void kernel_launch(void* const* d_in, const int* in_sizes, int n_in,
                              void* d_out, int out_size)
{
    const float* in[22];
    for (int i = 0; i < 22; i++) in[i] = (const float*)d_in[i];

    void *X_, *W6_, *bR_, *bI_;
    cudaGetSymbolAddress(&X_, g_X);
    cudaGetSymbolAddress(&W6_, g_W6);
    cudaGetSymbolAddress(&bR_, g_bR);
    cudaGetSymbolAddress(&bI_, g_bI);

    __nv_bfloat16* X = (__nv_bfloat16*)X_;
    __nv_bfloat16* W6 = (__nv_bfloat16*)W6_;
    float* bR = (float*)bR_;
    float* bI = (float*)bI_;

    cudaFuncSetAttribute(gemm_p, cudaFuncAttributeMaxDynamicSharedMemorySize, SMEM_BYTES);

    // weights: 6=Wq_r 7=bq_r 8=Wq_i 9=bq_i | 10..13 k | 14..17 v | 18..21 o
    pack6<<<1024, 256>>>(in[6],  in[8],  in[7],  in[9],  W6 + 0 * 6 * WVS, bR + 0 * K512, bI + 0 * K512);
    pack6<<<1024, 256>>>(in[10], in[12], in[11], in[13], W6 + 1 * 6 * WVS, bR + 1 * K512, bI + 1 * K512);
    pack6<<<1024, 256>>>(in[14], in[16], in[15], in[17], W6 + 2 * 6 * WVS, bR + 2 * K512, bI + 2 * K512);
    pack6<<<1024, 256>>>(in[18], in[20], in[19], in[21], W6 + 3 * 6 * WVS, bR + 3 * K512, bI + 3 * K512);

    // input splits (q, k, v)
    split3<<<8192, 256>>>(in[0], in[1], X + 0 * 6 * VS);
    split3<<<8192, 256>>>(in[2], in[3], X + 1 * 6 * VS);
    split3<<<8192, 256>>>(in[4], in[5], X + 2 * 6 * VS);

    // 9 QKV P-GEMMs in one launch
    gemm_p<<<dim3(Mrows / BM, K512 / BN, 9), 512, SMEM_BYTES>>>(0);

    // attention (fused QKV Gauss combine)
    attn_kernel<<<dim3(512, 8, 4), 128>>>();

    // 3 o-layer P-GEMMs, then combine into d_out
    gemm_p<<<dim3(Mrows / BM, K512 / BN, 3), 512, SMEM_BYTES>>>(1);
    combine_out<<<8192, 256>>>((float*)d_out);
}

// round 11
// speedup vs baseline: 2.2431x; 1.2152x over previous
#include <cuda_runtime.h>
#include <cuda_bf16.h>
#include <cuda_fp16.h>
#include <cstdint>

// ---------------- problem constants ----------------
constexpr int Mrows = 16384;          // B*C*T = 4*8*512
constexpr int K512  = 512;            // P-GEMM: M x 512 x 512

// GEMM tiling (proven R8/R10 geometry)
constexpr int BM = 128, BN = 256, BK = 32;
constexpr int KSTEPS = K512 / BK;     // 16

// smem rows padded to 40 halves = 80 B (20 words) — ldmatrix conflict-free (proven)
constexpr int ROWB = 80;

// bf16x3 stage (o-GEMM): Ahi, Alo, Bhi, Blo
constexpr int ST_AHI = 0;
constexpr int ST_ALO = ST_AHI + BM * ROWB;      // 10240
constexpr int ST_BHI = ST_ALO + BM * ROWB;      // 20480
constexpr int ST_BLO = ST_BHI + BN * ROWB;      // 40960
constexpr int STAGE  = ST_BLO + BN * ROWB;      // 61440
// fp16x2 stage (QKV): A (hi only), Bhi, Blo
constexpr int ST_FA  = 0;
constexpr int ST_FBH = ST_FA + BM * ROWB;       // 10240
constexpr int ST_FBL = ST_FBH + BN * ROWB;      // 30720
constexpr int STAGE_F = ST_FBL + BN * ROWB;     // 51200

constexpr int SMEM_BYTES = 2 * STAGE;           // 122880 (max of both)

constexpr size_t VS  = (size_t)Mrows * K512;    // X variant stride
constexpr size_t WVS = (size_t)K512 * K512;     // W variant stride

// ---------------- device scratch (allocation-free) ----------------
// fp16 QKV path: activations single-fp16 per variant (0=r 1=i 2=s), weights hi/lo
__device__ __half g_Xh[3][3][Mrows * K512];          // q,k,v splits (fp16, hi only)
__device__ __half g_Wf[3][6][K512 * K512];           // qkv weights: r_hi,r_lo,i_hi,i_lo,s_hi,s_lo
// bf16x3 o path (as R10)
__device__ __nv_bfloat16 g_A6[6][Mrows * K512];      // attention output splits (o input)
__device__ __nv_bfloat16 g_Wo[6][K512 * K512];       // o weights bf16 hi/lo x (r,i,s)
__device__ float g_bR[4][K512];                      // br - bi   (layers q,k,v,o)
__device__ float g_bI[4][K512];                      // br + bi
__device__ float g_P[9][Mrows * K512];               // QKV products: layer*3 + p
__device__ float g_Po[3][Mrows * K512];              // o-layer products

// ---------------- PTX helpers (family-portable only) ----------------
#define CP_ASYNC16(dst, src) \
    asm volatile("cp.async.cg.shared.global [%0], [%1], 16;" :: "r"(dst), "l"(src))
#define CP_COMMIT() asm volatile("cp.async.commit_group;")
#define CP_WAIT(n)  asm volatile("cp.async.wait_group %0;" :: "n"(n))

#define LDSM_X4(r0, r1, r2, r3, addr) \
    asm volatile("ldmatrix.sync.aligned.m8n8.x4.shared.b16 {%0,%1,%2,%3}, [%4];" \
        : "=r"(r0), "=r"(r1), "=r"(r2), "=r"(r3) : "r"(addr))

__device__ __forceinline__ void mma_bf16(float* d, const uint32_t* a, uint32_t b0, uint32_t b1) {
    asm volatile(
        "mma.sync.aligned.m16n8k16.row.col.f32.bf16.bf16.f32 "
        "{%0,%1,%2,%3}, {%4,%5,%6,%7}, {%8,%9}, {%0,%1,%2,%3};"
        : "+f"(d[0]), "+f"(d[1]), "+f"(d[2]), "+f"(d[3])
        : "r"(a[0]), "r"(a[1]), "r"(a[2]), "r"(a[3]), "r"(b0), "r"(b1));
}
__device__ __forceinline__ void mma_f16(float* d, const uint32_t* a, uint32_t b0, uint32_t b1) {
    asm volatile(
        "mma.sync.aligned.m16n8k16.row.col.f32.f16.f16.f32 "
        "{%0,%1,%2,%3}, {%4,%5,%6,%7}, {%8,%9}, {%0,%1,%2,%3};"
        : "+f"(d[0]), "+f"(d[1]), "+f"(d[2]), "+f"(d[3])
        : "r"(a[0]), "r"(a[1]), "r"(a[2]), "r"(a[3]), "r"(b0), "r"(b1));
}

// ============================================================================
// pack QKV weights: Wr, Wi, Ws=Wr+Wi as fp16 hi/lo; biases br-bi, br+bi
// ============================================================================
__global__ void pack_f(const float* __restrict__ Wr, const float* __restrict__ Wi,
                       const float* __restrict__ br, const float* __restrict__ bi,
                       __half* __restrict__ W6, float* __restrict__ bR,
                       float* __restrict__ bI)
{
    int idx = blockIdx.x * 256 + threadIdx.x;     // over 262144
    float vr = Wr[idx], vi = Wi[idx], vs = vr + vi;
    float vals[3] = {vr, vi, vs};
#pragma unroll
    for (int p = 0; p < 3; p++) {
        __half h = __float2half(vals[p]);
        W6[(size_t)(2 * p) * WVS + idx] = h;
        W6[(size_t)(2 * p + 1) * WVS + idx] = __float2half(vals[p] - __half2float(h));
    }
    if (idx < K512) {
        bR[idx] = br[idx] - bi[idx];
        bI[idx] = br[idx] + bi[idx];
    }
}

// ============================================================================
// pack o weights: bf16 hi/lo x (r, i, s)  (R10 path)
// ============================================================================
__global__ void pack_o(const float* __restrict__ Wr, const float* __restrict__ Wi,
                       const float* __restrict__ br, const float* __restrict__ bi,
                       float* __restrict__ bR, float* __restrict__ bI)
{
    int idx = blockIdx.x * 256 + threadIdx.x;
    float vr = Wr[idx], vi = Wi[idx], vs = vr + vi;
    float vals[3] = {vr, vi, vs};
#pragma unroll
    for (int p = 0; p < 3; p++) {
        __nv_bfloat16 h = __float2bfloat16(vals[p]);
        g_Wo[2 * p][idx] = h;
        g_Wo[2 * p + 1][idx] = __float2bfloat16(vals[p] - __bfloat162float(h));
    }
    if (idx < K512) {
        bR[idx] = br[idx] - bi[idx];
        bI[idx] = br[idx] + bi[idx];
    }
}

// ============================================================================
// split fp32 inputs into single fp16 for r, i, s=r+i
// ============================================================================
struct alignas(8) HF4 { __half v[4]; };

__global__ void split_f(const float* __restrict__ xr, const float* __restrict__ xi,
                        __half* __restrict__ X)
{
    size_t i4 = (size_t)(blockIdx.x * 256 + threadIdx.x) * 4;   // over Mrows*K512
    float4 vr = *(const float4*)(xr + i4);
    float4 vi = *(const float4*)(xi + i4);
    float ar[4] = {vr.x, vr.y, vr.z, vr.w};
    float ai[4] = {vi.x, vi.y, vi.z, vi.w};
    HF4 out[3];
#pragma unroll
    for (int j = 0; j < 4; j++) {
        out[0].v[j] = __float2half(ar[j]);
        out[1].v[j] = __float2half(ai[j]);
        out[2].v[j] = __float2half(ar[j] + ai[j]);
    }
#pragma unroll
    for (int v = 0; v < 3; v++)
        *(HF4*)(X + (size_t)v * VS + i4) = out[v];
}

// ============================================================================
// fp16x2 P-GEMM (QKV): P = A_v @ (W_hi + W_lo)^T     z = layer*3 + p
// ============================================================================
__global__ void __launch_bounds__(512, 1)
gemm_f(void)
{
    const int z = blockIdx.z;
    const int layer = z / 3, p = z - 3 * layer;
    const __half* Ah_g  = g_Xh[layer][p];
    const __half* Bhi_g = g_Wf[layer][2 * p];
    const __half* Blo_g = g_Wf[layer][2 * p + 1];
    float* Pout = g_P[z];

    extern __shared__ char smem[];
    const int tid = threadIdx.x;
    const int wid = tid >> 5, lane = tid & 31;
    const int wm = wid >> 2, wn = wid & 3;        // 4 x 4 warps, tile 32 x 64
    const int r = lane >> 2, c = lane & 3;
    const int bm = blockIdx.x * BM, bn = blockIdx.y * BN;

    const uint32_t sb = (uint32_t)__cvta_generic_to_shared(smem);

    const int arow = (lane & 7) + ((lane >> 3) & 1) * 8;
    const int akof = ((lane >> 4) & 1) * 16;
    const uint32_t a_off = (uint32_t)((wm * 32 + arow) * ROWB + akof);
    const int brow = (lane & 7) + ((lane >> 4) & 1) * 8;
    const int bkof = ((lane >> 3) & 1) * 16;
    const uint32_t b_off = (uint32_t)((wn * 64 + brow) * ROWB + bkof);

    float acc[2][8][4];
#pragma unroll
    for (int mi = 0; mi < 2; mi++)
#pragma unroll
        for (int nj = 0; nj < 8; nj++)
#pragma unroll
            for (int e = 0; e < 4; e++) acc[mi][nj][e] = 0.f;

    auto load_stage = [&](int s, int kt) {
        uint32_t base = sb + s * STAGE_F;
        {
            int row = tid >> 2, ch = tid & 3;
            CP_ASYNC16(base + ST_FA + row * ROWB + ch * 16,
                       Ah_g + (size_t)(bm + row) * K512 + kt + ch * 8);
        }
#pragma unroll
        for (int i = 0; i < 2; i++) {
            int j = tid + i * 512;
            int row = j >> 2, ch = j & 3;
            size_t go = (size_t)(bn + row) * K512 + kt + ch * 8;
            CP_ASYNC16(base + ST_FBH + row * ROWB + ch * 16, Bhi_g + go);
            CP_ASYNC16(base + ST_FBL + row * ROWB + ch * 16, Blo_g + go);
        }
        CP_COMMIT();
    };

    load_stage(0, 0);

    for (int s = 0; s < KSTEPS; s++) {
        if (s + 1 < KSTEPS) {
            load_stage((s + 1) & 1, (s + 1) * BK);
            CP_WAIT(1);
        } else {
            CP_WAIT(0);
        }
        __syncthreads();

        const uint32_t stb = sb + (s & 1) * STAGE_F;
#pragma unroll
        for (int kk = 0; kk < 2; kk++) {
            const uint32_t kb = stb + kk * 32;
            uint32_t ah[2][4];
#pragma unroll
            for (int mi = 0; mi < 2; mi++)
                LDSM_X4(ah[mi][0], ah[mi][1], ah[mi][2], ah[mi][3],
                        kb + ST_FA + a_off + mi * (16 * ROWB));
#pragma unroll
            for (int g = 0; g < 4; g++) {
                uint32_t bh[4], bl[4];
                LDSM_X4(bh[0], bh[1], bh[2], bh[3], kb + ST_FBH + b_off + g * (16 * ROWB));
                LDSM_X4(bl[0], bl[1], bl[2], bl[3], kb + ST_FBL + b_off + g * (16 * ROWB));
#pragma unroll
                for (int mi = 0; mi < 2; mi++) {
                    mma_f16(acc[mi][2 * g + 0], ah[mi], bh[0], bh[1]);
                    mma_f16(acc[mi][2 * g + 0], ah[mi], bl[0], bl[1]);
                    mma_f16(acc[mi][2 * g + 1], ah[mi], bh[2], bh[3]);
                    mma_f16(acc[mi][2 * g + 1], ah[mi], bl[2], bl[3]);
                }
            }
        }
        __syncthreads();
    }

#pragma unroll
    for (int mi = 0; mi < 2; mi++)
#pragma unroll
        for (int nj = 0; nj < 8; nj++) {
            int ncol = bn + wn * 64 + nj * 8 + 2 * c;
            int row0 = bm + wm * 32 + mi * 16 + r;
#pragma unroll
            for (int hrow = 0; hrow < 2; hrow++) {
                float2 o = make_float2(acc[mi][nj][2 * hrow + 0], acc[mi][nj][2 * hrow + 1]);
                *(float2*)&Pout[(size_t)(row0 + 8 * hrow) * K512 + ncol] = o;
            }
        }
}

// ============================================================================
// bf16x3 P-GEMM (o layer, R10 path): P = A6 @ Wo^T (hh + hl + lh)   z = p
// ============================================================================
__global__ void __launch_bounds__(512, 1)
gemm_o(void)
{
    const int z = blockIdx.z;
    const __nv_bfloat16* Ahi_g = g_A6[2 * z];
    const __nv_bfloat16* Alo_g = g_A6[2 * z + 1];
    const __nv_bfloat16* Bhi_g = g_Wo[2 * z];
    const __nv_bfloat16* Blo_g = g_Wo[2 * z + 1];
    float* Pout = g_Po[z];

    extern __shared__ char smem[];
    const int tid = threadIdx.x;
    const int wid = tid >> 5, lane = tid & 31;
    const int wm = wid >> 2, wn = wid & 3;
    const int r = lane >> 2, c = lane & 3;
    const int bm = blockIdx.x * BM, bn = blockIdx.y * BN;

    const uint32_t sb = (uint32_t)__cvta_generic_to_shared(smem);

    const int arow = (lane & 7) + ((lane >> 3) & 1) * 8;
    const int akof = ((lane >> 4) & 1) * 16;
    const uint32_t a_off = (uint32_t)((wm * 32 + arow) * ROWB + akof);
    const int brow = (lane & 7) + ((lane >> 4) & 1) * 8;
    const int bkof = ((lane >> 3) & 1) * 16;
    const uint32_t b_off = (uint32_t)((wn * 64 + brow) * ROWB + bkof);

    float acc[2][8][4];
#pragma unroll
    for (int mi = 0; mi < 2; mi++)
#pragma unroll
        for (int nj = 0; nj < 8; nj++)
#pragma unroll
            for (int e = 0; e < 4; e++) acc[mi][nj][e] = 0.f;

    auto load_stage = [&](int s, int kt) {
        uint32_t base = sb + s * STAGE;
        {
            int row = tid >> 2, ch = tid & 3;
            size_t go = (size_t)(bm + row) * K512 + kt + ch * 8;
            CP_ASYNC16(base + ST_AHI + row * ROWB + ch * 16, Ahi_g + go);
            CP_ASYNC16(base + ST_ALO + row * ROWB + ch * 16, Alo_g + go);
        }
#pragma unroll
        for (int i = 0; i < 2; i++) {
            int j = tid + i * 512;
            int row = j >> 2, ch = j & 3;
            size_t go = (size_t)(bn + row) * K512 + kt + ch * 8;
            CP_ASYNC16(base + ST_BHI + row * ROWB + ch * 16, Bhi_g + go);
            CP_ASYNC16(base + ST_BLO + row * ROWB + ch * 16, Blo_g + go);
        }
        CP_COMMIT();
    };

    load_stage(0, 0);

    for (int s = 0; s < KSTEPS; s++) {
        if (s + 1 < KSTEPS) {
            load_stage((s + 1) & 1, (s + 1) * BK);
            CP_WAIT(1);
        } else {
            CP_WAIT(0);
        }
        __syncthreads();

        const uint32_t stb = sb + (s & 1) * STAGE;
#pragma unroll
        for (int kk = 0; kk < 2; kk++) {
            const uint32_t kb = stb + kk * 32;
            uint32_t ah[2][4], al[2][4];
#pragma unroll
            for (int mi = 0; mi < 2; mi++) {
                LDSM_X4(ah[mi][0], ah[mi][1], ah[mi][2], ah[mi][3],
                        kb + ST_AHI + a_off + mi * (16 * ROWB));
                LDSM_X4(al[mi][0], al[mi][1], al[mi][2], al[mi][3],
                        kb + ST_ALO + a_off + mi * (16 * ROWB));
            }
#pragma unroll
            for (int g = 0; g < 4; g++) {
                uint32_t bh[4], bl[4];
                LDSM_X4(bh[0], bh[1], bh[2], bh[3], kb + ST_BHI + b_off + g * (16 * ROWB));
                LDSM_X4(bl[0], bl[1], bl[2], bl[3], kb + ST_BLO + b_off + g * (16 * ROWB));
#pragma unroll
                for (int mi = 0; mi < 2; mi++) {
                    mma_bf16(acc[mi][2 * g + 0], ah[mi], bh[0], bh[1]);
                    mma_bf16(acc[mi][2 * g + 0], ah[mi], bl[0], bl[1]);
                    mma_bf16(acc[mi][2 * g + 0], al[mi], bh[0], bh[1]);
                    mma_bf16(acc[mi][2 * g + 1], ah[mi], bh[2], bh[3]);
                    mma_bf16(acc[mi][2 * g + 1], ah[mi], bl[2], bl[3]);
                    mma_bf16(acc[mi][2 * g + 1], al[mi], bh[2], bh[3]);
                }
            }
        }
        __syncthreads();
    }

#pragma unroll
    for (int mi = 0; mi < 2; mi++)
#pragma unroll
        for (int nj = 0; nj < 8; nj++) {
            int ncol = bn + wn * 64 + nj * 8 + 2 * c;
            int row0 = bm + wm * 32 + mi * 16 + r;
#pragma unroll
            for (int hrow = 0; hrow < 2; hrow++) {
                float2 o = make_float2(acc[mi][nj][2 * hrow + 0], acc[mi][nj][2 * hrow + 1]);
                *(float2*)&Pout[(size_t)(row0 + 8 * hrow) * K512 + ncol] = o;
            }
        }
}

// ============================================================================
// channel attention with fused Gauss combine of Q/K/V (reads g_P), writes
// o-GEMM input splits g_A6 (bf16 hi/lo x r,i,s)
// ============================================================================
__global__ void attn_kernel()
{
    __shared__ float sm[6][8][68];
    __shared__ float ssr[8][9], ssi[8][9];

    const int t = blockIdx.x, h = blockIdx.y, b = blockIdx.z;
    const int tid = threadIdx.x;

    {
        int cch = tid >> 4, d4 = (tid & 15) << 2;
        size_t m = ((size_t)(b * 8 + cch) * 512 + t);
        size_t off = m * K512 + h * 64 + d4;
        int col = h * 64 + d4;

#pragma unroll
        for (int layer = 0; layer < 3; layer++) {
            float4 p1 = *(const float4*)&g_P[layer * 3 + 0][off];
            float4 p2 = *(const float4*)&g_P[layer * 3 + 1][off];
            float4 p3 = *(const float4*)&g_P[layer * 3 + 2][off];
            float4 br = *(const float4*)&g_bR[layer][col];
            float4 bi = *(const float4*)&g_bI[layer][col];
            float4 yr, yi;
            yr.x = p1.x - p2.x + br.x;  yi.x = p3.x - p1.x - p2.x + bi.x;
            yr.y = p1.y - p2.y + br.y;  yi.y = p3.y - p1.y - p2.y + bi.y;
            yr.z = p1.z - p2.z + br.z;  yi.z = p3.z - p1.z - p2.z + bi.z;
            yr.w = p1.w - p2.w + br.w;  yi.w = p3.w - p1.w - p2.w + bi.w;
            if (layer == 2) {
                yr.x = yr.x >= 0.f ? yr.x : 0.01f * yr.x;
                yr.y = yr.y >= 0.f ? yr.y : 0.01f * yr.y;
                yr.z = yr.z >= 0.f ? yr.z : 0.01f * yr.z;
                yr.w = yr.w >= 0.f ? yr.w : 0.01f * yr.w;
                yi.x = yi.x >= 0.f ? yi.x : 0.01f * yi.x;
                yi.y = yi.y >= 0.f ? yi.y : 0.01f * yi.y;
                yi.z = yi.z >= 0.f ? yi.z : 0.01f * yi.z;
                yi.w = yi.w >= 0.f ? yi.w : 0.01f * yi.w;
            }
            *(float4*)&sm[2 * layer + 0][cch][d4] = yr;
            *(float4*)&sm[2 * layer + 1][cch][d4] = yi;
        }
    }
    __syncthreads();

    if (tid < 64) {
        int cc = tid >> 3, e = tid & 7;
        float ar = 0.f, ai = 0.f;
#pragma unroll 8
        for (int d = 0; d < 64; d++) {
            float qr = sm[0][cc][d], qi = sm[1][cc][d];
            float kr = sm[2][e][d],  ki = sm[3][e][d];
            ar = fmaf(qr, kr, fmaf(qi, ki, ar));
            ai = fmaf(qr, ki, fmaf(-qi, kr, ai));
        }
        ssr[cc][e] = ar * 0.125f;
        ssi[cc][e] = ai * 0.125f;
    }
    __syncthreads();

#pragma unroll
    for (int i = 0; i < 4; i++) {
        int idx = tid + i * 128;
        int cc = idx >> 6, d = idx & 63;
        float xr = 0.f, xi = 0.f;
#pragma unroll
        for (int e = 0; e < 8; e++) {
            float sr_ = ssr[cc][e], si_ = ssi[cc][e];
            float vr = sm[4][e][d], vi = sm[5][e][d];
            xr = fmaf(sr_, vr, fmaf(-si_, vi, xr));
            xi = fmaf(si_, vr, fmaf(sr_, vi, xi));
        }
        xr = xr >= 0.f ? xr : 0.01f * xr;
        xi = xi >= 0.f ? xi : 0.01f * xi;
        float xs = xr + xi;
        size_t mrow = (size_t)(b * 8 + cc) * 512 + t;
        size_t o = mrow * K512 + h * 64 + d;
        float vals[3] = {xr, xi, xs};
#pragma unroll
        for (int p = 0; p < 3; p++) {
            __nv_bfloat16 hh = __float2bfloat16(vals[p]);
            g_A6[2 * p][o] = hh;
            g_A6[2 * p + 1][o] = __float2bfloat16(vals[p] - __bfloat162float(hh));
        }
    }
}

// ============================================================================
// o-layer Gauss combine: d_out = [Yr | Yi] from g_Po + biases
// ============================================================================
__global__ void combine_out(float* __restrict__ out)
{
    size_t i4 = (size_t)(blockIdx.x * 256 + threadIdx.x) * 4;
    int col = (int)(i4 & 511);
    float4 p1 = *(const float4*)&g_Po[0][i4];
    float4 p2 = *(const float4*)&g_Po[1][i4];
    float4 p3 = *(const float4*)&g_Po[2][i4];
    float4 br = *(const float4*)&g_bR[3][col];
    float4 bi = *(const float4*)&g_bI[3][col];
    float4 yr, yi;
    yr.x = p1.x - p2.x + br.x;  yi.x = p3.x - p1.x - p2.x + bi.x;
    yr.y = p1.y - p2.y + br.y;  yi.y = p3.y - p1.y - p2.y + bi.y;
    yr.z = p1.z - p2.z + br.z;  yi.z = p3.z - p1.z - p2.z + bi.z;
    yr.w = p1.w - p2.w + br.w;  yi.w = p3.w - p1.w - p2.w + bi.w;
    *(float4*)&out[i4] = yr;
    *(float4*)&out[(size_t)Mrows * K512 + i4] = yi;
}

// ============================================================================
// host side
// ============================================================================
extern "C" void kernel_launch(void* const* d_in, const int* in_sizes, int n_in,
                              void* d_out, int out_size)
{
    const float* in[22];
    for (int i = 0; i < 22; i++) in[i] = (const float*)d_in[i];

    void *Xh_, *Wf_, *bR_, *bI_;
    cudaGetSymbolAddress(&Xh_, g_Xh);
    cudaGetSymbolAddress(&Wf_, g_Wf);
    cudaGetSymbolAddress(&bR_, g_bR);
    cudaGetSymbolAddress(&bI_, g_bI);

    __half* Xh = (__half*)Xh_;
    __half* Wf = (__half*)Wf_;
    float* bR = (float*)bR_;
    float* bI = (float*)bI_;

    cudaFuncSetAttribute(gemm_f, cudaFuncAttributeMaxDynamicSharedMemorySize, SMEM_BYTES);
    cudaFuncSetAttribute(gemm_o, cudaFuncAttributeMaxDynamicSharedMemorySize, SMEM_BYTES);

    // weights: 6=Wq_r 7=bq_r 8=Wq_i 9=bq_i | 10..13 k | 14..17 v | 18..21 o
    pack_f<<<1024, 256>>>(in[6],  in[8],  in[7],  in[9],  Wf + 0 * 6 * WVS, bR + 0 * K512, bI + 0 * K512);
    pack_f<<<1024, 256>>>(in[10], in[12], in[11], in[13], Wf + 1 * 6 * WVS, bR + 1 * K512, bI + 1 * K512);
    pack_f<<<1024, 256>>>(in[14], in[16], in[15], in[17], Wf + 2 * 6 * WVS, bR + 2 * K512, bI + 2 * K512);
    pack_o<<<1024, 256>>>(in[18], in[20], in[19], in[21], bR + 3 * K512, bI + 3 * K512);

    // input splits (q, k, v) -> fp16 r,i,s
    split_f<<<8192, 256>>>(in[0], in[1], Xh + 0 * 3 * VS);
    split_f<<<8192, 256>>>(in[2], in[3], Xh + 1 * 3 * VS);
    split_f<<<8192, 256>>>(in[4], in[5], Xh + 2 * 3 * VS);

    // 9 QKV P-GEMMs (fp16x2) in one launch
    gemm_f<<<dim3(Mrows / BM, K512 / BN, 9), 512, SMEM_BYTES>>>();

    // attention (fused QKV Gauss combine)
    attn_kernel<<<dim3(512, 8, 4), 128>>>();

    // 3 o-layer P-GEMMs (bf16x3), then combine into d_out
    gemm_o<<<dim3(Mrows / BM, K512 / BN, 3), 512, SMEM_BYTES>>>();
    combine_out<<<8192, 256>>>((float*)d_out);
}

// round 12
// speedup vs baseline: 2.4068x; 1.0730x over previous
#include <cuda_runtime.h>
#include <cuda_bf16.h>
#include <cuda_fp16.h>
#include <cstdint>

// ---------------- problem constants ----------------
constexpr int Mrows = 16384;          // B*C*T = 4*8*512
constexpr int K512  = 512;            // P-GEMM: M x 512 x 512

// GEMM tiling (proven R8/R10 geometry)
constexpr int BM = 128, BN = 256, BK = 32;
constexpr int KSTEPS = K512 / BK;     // 16

// smem rows padded to 40 halves = 80 B (20 words) — ldmatrix conflict-free (proven)
constexpr int ROWB = 80;

// fp16x2 stage: A (single), Bhi, Blo
constexpr int ST_FA  = 0;
constexpr int ST_FBH = ST_FA + BM * ROWB;       // 10240
constexpr int ST_FBL = ST_FBH + BN * ROWB;      // 30720
constexpr int STAGE_F = ST_FBL + BN * ROWB;     // 51200

constexpr int SMEM_BYTES = 2 * STAGE_F;         // 102400

constexpr size_t VS  = (size_t)Mrows * K512;    // X variant stride
constexpr size_t WVS = (size_t)K512 * K512;     // W variant stride

// ---------------- device scratch (allocation-free) ----------------
// fp16x2 everywhere: activations single-fp16 per variant (0=r 1=i 2=s), weights hi/lo
__device__ __half g_Xh[3][3][Mrows * K512];          // q,k,v splits (fp16)
__device__ __half g_Ao[3][Mrows * K512];             // attention output splits (o input, fp16)
__device__ __half g_Wf[4][6][K512 * K512];           // weights q,k,v,o: r_hi,r_lo,i_hi,i_lo,s_hi,s_lo
__device__ float g_bR[4][K512];                      // br - bi   (layers q,k,v,o)
__device__ float g_bI[4][K512];                      // br + bi
__device__ float g_P[9][Mrows * K512];               // QKV products: layer*3 + p
__device__ float g_Po[3][Mrows * K512];              // o-layer products

// ---------------- PTX helpers (family-portable only) ----------------
#define CP_ASYNC16(dst, src) \
    asm volatile("cp.async.cg.shared.global [%0], [%1], 16;" :: "r"(dst), "l"(src))
#define CP_COMMIT() asm volatile("cp.async.commit_group;")
#define CP_WAIT(n)  asm volatile("cp.async.wait_group %0;" :: "n"(n))

#define LDSM_X4(r0, r1, r2, r3, addr) \
    asm volatile("ldmatrix.sync.aligned.m8n8.x4.shared.b16 {%0,%1,%2,%3}, [%4];" \
        : "=r"(r0), "=r"(r1), "=r"(r2), "=r"(r3) : "r"(addr))

__device__ __forceinline__ void mma_f16(float* d, const uint32_t* a, uint32_t b0, uint32_t b1) {
    asm volatile(
        "mma.sync.aligned.m16n8k16.row.col.f32.f16.f16.f32 "
        "{%0,%1,%2,%3}, {%4,%5,%6,%7}, {%8,%9}, {%0,%1,%2,%3};"
        : "+f"(d[0]), "+f"(d[1]), "+f"(d[2]), "+f"(d[3])
        : "r"(a[0]), "r"(a[1]), "r"(a[2]), "r"(a[3]), "r"(b0), "r"(b1));
}

// ============================================================================
// pack weights: Wr, Wi, Ws=Wr+Wi as fp16 hi/lo; biases br-bi, br+bi
// ============================================================================
__global__ void pack_f(const float* __restrict__ Wr, const float* __restrict__ Wi,
                       const float* __restrict__ br, const float* __restrict__ bi,
                       __half* __restrict__ W6, float* __restrict__ bR,
                       float* __restrict__ bI)
{
    int idx = blockIdx.x * 256 + threadIdx.x;     // over 262144
    float vr = Wr[idx], vi = Wi[idx], vs = vr + vi;
    float vals[3] = {vr, vi, vs};
#pragma unroll
    for (int p = 0; p < 3; p++) {
        __half h = __float2half(vals[p]);
        W6[(size_t)(2 * p) * WVS + idx] = h;
        W6[(size_t)(2 * p + 1) * WVS + idx] = __float2half(vals[p] - __half2float(h));
    }
    if (idx < K512) {
        bR[idx] = br[idx] - bi[idx];
        bI[idx] = br[idx] + bi[idx];
    }
}

// ============================================================================
// split fp32 inputs into single fp16 for r, i, s=r+i
// ============================================================================
struct alignas(8) HF4 { __half v[4]; };

__global__ void split_f(const float* __restrict__ xr, const float* __restrict__ xi,
                        __half* __restrict__ X)
{
    size_t i4 = (size_t)(blockIdx.x * 256 + threadIdx.x) * 4;   // over Mrows*K512
    float4 vr = *(const float4*)(xr + i4);
    float4 vi = *(const float4*)(xi + i4);
    float ar[4] = {vr.x, vr.y, vr.z, vr.w};
    float ai[4] = {vi.x, vi.y, vi.z, vi.w};
    HF4 out[3];
#pragma unroll
    for (int j = 0; j < 4; j++) {
        out[0].v[j] = __float2half(ar[j]);
        out[1].v[j] = __float2half(ai[j]);
        out[2].v[j] = __float2half(ar[j] + ai[j]);
    }
#pragma unroll
    for (int v = 0; v < 3; v++)
        *(HF4*)(X + (size_t)v * VS + i4) = out[v];
}

// ============================================================================
// fp16x2 P-GEMM: P = A_v @ (W_hi + W_lo)^T
// mode 0: QKV (z = layer*3 + p), mode 1: o-layer (z = p)
// BM=128 BN=256 BK=32, 512 threads (4x4 warps, warp tile 32x64).
// ============================================================================
__global__ void __launch_bounds__(512, 1)
gemm_f(int mode)
{
    const int z = blockIdx.z;
    const __half *Ah_g, *Bhi_g, *Blo_g;
    float* Pout;
    if (mode == 0) {
        int layer = z / 3, p = z - 3 * layer;
        Ah_g  = g_Xh[layer][p];
        Bhi_g = g_Wf[layer][2 * p];
        Blo_g = g_Wf[layer][2 * p + 1];
        Pout  = g_P[z];
    } else {
        Ah_g  = g_Ao[z];
        Bhi_g = g_Wf[3][2 * z];
        Blo_g = g_Wf[3][2 * z + 1];
        Pout  = g_Po[z];
    }

    extern __shared__ char smem[];
    const int tid = threadIdx.x;
    const int wid = tid >> 5, lane = tid & 31;
    const int wm = wid >> 2, wn = wid & 3;        // 4 x 4 warps, tile 32 x 64
    const int r = lane >> 2, c = lane & 3;
    const int bm = blockIdx.x * BM, bn = blockIdx.y * BN;

    const uint32_t sb = (uint32_t)__cvta_generic_to_shared(smem);

    const int arow = (lane & 7) + ((lane >> 3) & 1) * 8;
    const int akof = ((lane >> 4) & 1) * 16;
    const uint32_t a_off = (uint32_t)((wm * 32 + arow) * ROWB + akof);
    const int brow = (lane & 7) + ((lane >> 4) & 1) * 8;
    const int bkof = ((lane >> 3) & 1) * 16;
    const uint32_t b_off = (uint32_t)((wn * 64 + brow) * ROWB + bkof);

    float acc[2][8][4];
#pragma unroll
    for (int mi = 0; mi < 2; mi++)
#pragma unroll
        for (int nj = 0; nj < 8; nj++)
#pragma unroll
            for (int e = 0; e < 4; e++) acc[mi][nj][e] = 0.f;

    auto load_stage = [&](int s, int kt) {
        uint32_t base = sb + s * STAGE_F;
        {
            int row = tid >> 2, ch = tid & 3;
            CP_ASYNC16(base + ST_FA + row * ROWB + ch * 16,
                       Ah_g + (size_t)(bm + row) * K512 + kt + ch * 8);
        }
#pragma unroll
        for (int i = 0; i < 2; i++) {
            int j = tid + i * 512;
            int row = j >> 2, ch = j & 3;
            size_t go = (size_t)(bn + row) * K512 + kt + ch * 8;
            CP_ASYNC16(base + ST_FBH + row * ROWB + ch * 16, Bhi_g + go);
            CP_ASYNC16(base + ST_FBL + row * ROWB + ch * 16, Blo_g + go);
        }
        CP_COMMIT();
    };

    load_stage(0, 0);

    for (int s = 0; s < KSTEPS; s++) {
        if (s + 1 < KSTEPS) {
            load_stage((s + 1) & 1, (s + 1) * BK);
            CP_WAIT(1);
        } else {
            CP_WAIT(0);
        }
        __syncthreads();

        const uint32_t stb = sb + (s & 1) * STAGE_F;
#pragma unroll
        for (int kk = 0; kk < 2; kk++) {
            const uint32_t kb = stb + kk * 32;
            uint32_t ah[2][4];
#pragma unroll
            for (int mi = 0; mi < 2; mi++)
                LDSM_X4(ah[mi][0], ah[mi][1], ah[mi][2], ah[mi][3],
                        kb + ST_FA + a_off + mi * (16 * ROWB));
#pragma unroll
            for (int g = 0; g < 4; g++) {
                uint32_t bh[4], bl[4];
                LDSM_X4(bh[0], bh[1], bh[2], bh[3], kb + ST_FBH + b_off + g * (16 * ROWB));
                LDSM_X4(bl[0], bl[1], bl[2], bl[3], kb + ST_FBL + b_off + g * (16 * ROWB));
#pragma unroll
                for (int mi = 0; mi < 2; mi++) {
                    mma_f16(acc[mi][2 * g + 0], ah[mi], bh[0], bh[1]);
                    mma_f16(acc[mi][2 * g + 0], ah[mi], bl[0], bl[1]);
                    mma_f16(acc[mi][2 * g + 1], ah[mi], bh[2], bh[3]);
                    mma_f16(acc[mi][2 * g + 1], ah[mi], bl[2], bl[3]);
                }
            }
        }
        __syncthreads();
    }

#pragma unroll
    for (int mi = 0; mi < 2; mi++)
#pragma unroll
        for (int nj = 0; nj < 8; nj++) {
            int ncol = bn + wn * 64 + nj * 8 + 2 * c;
            int row0 = bm + wm * 32 + mi * 16 + r;
#pragma unroll
            for (int hrow = 0; hrow < 2; hrow++) {
                float2 o = make_float2(acc[mi][nj][2 * hrow + 0], acc[mi][nj][2 * hrow + 1]);
                *(float2*)&Pout[(size_t)(row0 + 8 * hrow) * K512 + ncol] = o;
            }
        }
}

// ============================================================================
// channel attention with fused Gauss combine of Q/K/V (reads g_P fp32),
// writes o-GEMM input splits g_Ao (fp16 r,i,s)
// ============================================================================
__global__ void attn_kernel()
{
    __shared__ float sm[6][8][68];
    __shared__ float ssr[8][9], ssi[8][9];

    const int t = blockIdx.x, h = blockIdx.y, b = blockIdx.z;
    const int tid = threadIdx.x;

    {
        int cch = tid >> 4, d4 = (tid & 15) << 2;
        size_t m = ((size_t)(b * 8 + cch) * 512 + t);
        size_t off = m * K512 + h * 64 + d4;
        int col = h * 64 + d4;

#pragma unroll
        for (int layer = 0; layer < 3; layer++) {
            float4 p1 = *(const float4*)&g_P[layer * 3 + 0][off];
            float4 p2 = *(const float4*)&g_P[layer * 3 + 1][off];
            float4 p3 = *(const float4*)&g_P[layer * 3 + 2][off];
            float4 br = *(const float4*)&g_bR[layer][col];
            float4 bi = *(const float4*)&g_bI[layer][col];
            float4 yr, yi;
            yr.x = p1.x - p2.x + br.x;  yi.x = p3.x - p1.x - p2.x + bi.x;
            yr.y = p1.y - p2.y + br.y;  yi.y = p3.y - p1.y - p2.y + bi.y;
            yr.z = p1.z - p2.z + br.z;  yi.z = p3.z - p1.z - p2.z + bi.z;
            yr.w = p1.w - p2.w + br.w;  yi.w = p3.w - p1.w - p2.w + bi.w;
            if (layer == 2) {
                yr.x = yr.x >= 0.f ? yr.x : 0.01f * yr.x;
                yr.y = yr.y >= 0.f ? yr.y : 0.01f * yr.y;
                yr.z = yr.z >= 0.f ? yr.z : 0.01f * yr.z;
                yr.w = yr.w >= 0.f ? yr.w : 0.01f * yr.w;
                yi.x = yi.x >= 0.f ? yi.x : 0.01f * yi.x;
                yi.y = yi.y >= 0.f ? yi.y : 0.01f * yi.y;
                yi.z = yi.z >= 0.f ? yi.z : 0.01f * yi.z;
                yi.w = yi.w >= 0.f ? yi.w : 0.01f * yi.w;
            }
            *(float4*)&sm[2 * layer + 0][cch][d4] = yr;
            *(float4*)&sm[2 * layer + 1][cch][d4] = yi;
        }
    }
    __syncthreads();

    if (tid < 64) {
        int cc = tid >> 3, e = tid & 7;
        float ar = 0.f, ai = 0.f;
#pragma unroll 8
        for (int d = 0; d < 64; d++) {
            float qr = sm[0][cc][d], qi = sm[1][cc][d];
            float kr = sm[2][e][d],  ki = sm[3][e][d];
            ar = fmaf(qr, kr, fmaf(qi, ki, ar));
            ai = fmaf(qr, ki, fmaf(-qi, kr, ai));
        }
        ssr[cc][e] = ar * 0.125f;
        ssi[cc][e] = ai * 0.125f;
    }
    __syncthreads();

#pragma unroll
    for (int i = 0; i < 4; i++) {
        int idx = tid + i * 128;
        int cc = idx >> 6, d = idx & 63;
        float xr = 0.f, xi = 0.f;
#pragma unroll
        for (int e = 0; e < 8; e++) {
            float sr_ = ssr[cc][e], si_ = ssi[cc][e];
            float vr = sm[4][e][d], vi = sm[5][e][d];
            xr = fmaf(sr_, vr, fmaf(-si_, vi, xr));
            xi = fmaf(si_, vr, fmaf(sr_, vi, xi));
        }
        xr = xr >= 0.f ? xr : 0.01f * xr;
        xi = xi >= 0.f ? xi : 0.01f * xi;
        size_t mrow = (size_t)(b * 8 + cc) * 512 + t;
        size_t o = mrow * K512 + h * 64 + d;
        g_Ao[0][o] = __float2half(xr);
        g_Ao[1][o] = __float2half(xi);
        g_Ao[2][o] = __float2half(xr + xi);
    }
}

// ============================================================================
// o-layer Gauss combine: d_out = [Yr | Yi] from g_Po + biases
// ============================================================================
__global__ void combine_out(float* __restrict__ out)
{
    size_t i4 = (size_t)(blockIdx.x * 256 + threadIdx.x) * 4;
    int col = (int)(i4 & 511);
    float4 p1 = *(const float4*)&g_Po[0][i4];
    float4 p2 = *(const float4*)&g_Po[1][i4];
    float4 p3 = *(const float4*)&g_Po[2][i4];
    float4 br = *(const float4*)&g_bR[3][col];
    float4 bi = *(const float4*)&g_bI[3][col];
    float4 yr, yi;
    yr.x = p1.x - p2.x + br.x;  yi.x = p3.x - p1.x - p2.x + bi.x;
    yr.y = p1.y - p2.y + br.y;  yi.y = p3.y - p1.y - p2.y + bi.y;
    yr.z = p1.z - p2.z + br.z;  yi.z = p3.z - p1.z - p2.z + bi.z;
    yr.w = p1.w - p2.w + br.w;  yi.w = p3.w - p1.w - p2.w + bi.w;
    *(float4*)&out[i4] = yr;
    *(float4*)&out[(size_t)Mrows * K512 + i4] = yi;
}

// ============================================================================
// host side
// ============================================================================
extern "C" void kernel_launch(void* const* d_in, const int* in_sizes, int n_in,
                              void* d_out, int out_size)
{
    const float* in[22];
    for (int i = 0; i < 22; i++) in[i] = (const float*)d_in[i];

    void *Xh_, *Wf_, *bR_, *bI_;
    cudaGetSymbolAddress(&Xh_, g_Xh);
    cudaGetSymbolAddress(&Wf_, g_Wf);
    cudaGetSymbolAddress(&bR_, g_bR);
    cudaGetSymbolAddress(&bI_, g_bI);

    __half* Xh = (__half*)Xh_;
    __half* Wf = (__half*)Wf_;
    float* bR = (float*)bR_;
    float* bI = (float*)bI_;

    cudaFuncSetAttribute(gemm_f, cudaFuncAttributeMaxDynamicSharedMemorySize, SMEM_BYTES);

    // weights: 6=Wq_r 7=bq_r 8=Wq_i 9=bq_i | 10..13 k | 14..17 v | 18..21 o
    pack_f<<<1024, 256>>>(in[6],  in[8],  in[7],  in[9],  Wf + 0 * 6 * WVS, bR + 0 * K512, bI + 0 * K512);
    pack_f<<<1024, 256>>>(in[10], in[12], in[11], in[13], Wf + 1 * 6 * WVS, bR + 1 * K512, bI + 1 * K512);
    pack_f<<<1024, 256>>>(in[14], in[16], in[15], in[17], Wf + 2 * 6 * WVS, bR + 2 * K512, bI + 2 * K512);
    pack_f<<<1024, 256>>>(in[18], in[20], in[19], in[21], Wf + 3 * 6 * WVS, bR + 3 * K512, bI + 3 * K512);

    // input splits (q, k, v) -> fp16 r,i,s
    split_f<<<8192, 256>>>(in[0], in[1], Xh + 0 * 3 * VS);
    split_f<<<8192, 256>>>(in[2], in[3], Xh + 1 * 3 * VS);
    split_f<<<8192, 256>>>(in[4], in[5], Xh + 2 * 3 * VS);

    // 9 QKV P-GEMMs (fp16x2) in one launch
    gemm_f<<<dim3(Mrows / BM, K512 / BN, 9), 512, SMEM_BYTES>>>(0);

    // attention (fused QKV Gauss combine)
    attn_kernel<<<dim3(512, 8, 4), 128>>>();

    // 3 o-layer P-GEMMs (fp16x2), then combine into d_out
    gemm_f<<<dim3(Mrows / BM, K512 / BN, 3), 512, SMEM_BYTES>>>(1);
    combine_out<<<8192, 256>>>((float*)d_out);
}